// round 10
// baseline (speedup 1.0000x reference)
#include <cuda_runtime.h>
#include <math.h>

// Inputs (metadata order): y[16M] f32, mu[16M] f32, std[16M] f32, idx[200*100] i32
// Output: 1 x f32 (KL scalar)
//
// Converged best-of-session design:
//   - 200 blocks x 128 threads; threads 0..99 each gather one (y,mu,sd)
//     triple via a sequentially-coalesced idx row read (chain head).
//   - Per-sample chi-square q reduced in-block (shfl tree + 4-word smem fold).
//   - Shifted moments (q-K), (q-K)^2 folded into fp32 global accumulators
//     with release-ordered REDs — no MEMBARs anywhere.
//   - acq_rel ticket elects the last block; winner reads both moments with
//     one ld.acquire.gpu.v2.f32 and computes KL with fp32 MUFU math.
//   - Scratch reset by winner -> deterministic across graph replays.
// Wall time is pinned at the harness graph-replay floor (~8.7 us); the
// kernel's dependent chain is minimal for a gather-defined reduction.

#define NUM_SAMPLES 200
#define KDOF 100

struct __align__(8) Moments { float s1, s2; };
__device__ Moments      g_m = {0.0f, 0.0f};
__device__ unsigned int g_count = 0;

__device__ __forceinline__ void red_release_f32(float* addr, float val) {
    asm volatile("red.release.gpu.global.add.f32 [%0], %1;"
                 :: "l"(addr), "f"(val) : "memory");
}
__device__ __forceinline__ unsigned int ticket_acq_rel(unsigned int* addr) {
    unsigned int old;
    asm volatile("atom.acq_rel.gpu.global.add.u32 %0, [%1], 1;"
                 : "=r"(old) : "l"(addr) : "memory");
    return old;
}
__device__ __forceinline__ float2 ld_acquire_v2(const Moments* addr) {
    float2 v;
    asm volatile("ld.acquire.gpu.global.v2.f32 {%0, %1}, [%2];"
                 : "=f"(v.x), "=f"(v.y) : "l"(addr) : "memory");
    return v;
}

__global__ void __launch_bounds__(128) fused_chi2_kl_kernel(
    const float* __restrict__ y,
    const float* __restrict__ mu,
    const float* __restrict__ sd,
    const int*   __restrict__ idx,
    float*       __restrict__ out)
{
    const int s = blockIdx.x;
    const int t = threadIdx.x;

    // ---- Phase 1: per-sample chi-square statistic ----
    float v = 0.0f;
    if (t < KDOF) {
        const int i = idx[s * KDOF + t];      // coalesced 400B row, chain head
        // three independent gathers -> MLP=3 per thread
        const float d = __fdividef(y[i] - mu[i], sd[i]);
        v = d * d;
    }

    #pragma unroll
    for (int o = 16; o > 0; o >>= 1)
        v += __shfl_down_sync(0xFFFFFFFFu, v, o);

    __shared__ float sm[4];
    if ((t & 31) == 0) sm[t >> 5] = v;
    __syncthreads();

    if (t != 0) return;

    // Shifted statistic p = q - K (kills cancellation in the var formula).
    const float p = (sm[0] + sm[1] + sm[2] + sm[3]) - (float)KDOF;

    red_release_f32(&g_m.s1, p);
    red_release_f32(&g_m.s2, p * p);

    if (ticket_acq_rel(&g_count) != NUM_SAMPLES - 1u) return;

    // ---- Phase 2 (single thread, last block to tick): KL ----
    const float2 m = ld_acquire_v2(&g_m);     // both sums, one round-trip

    const float inv_n = 1.0f / (float)NUM_SAMPLES;
    const float dm    = m.x * inv_n;                          // emp_mu - K
    const float var   = (m.y - m.x * m.x * inv_n)
                        * (1.0f / (float)(NUM_SAMPLES - 1));  // unbiased var
    const float two_k = 2.0f * (float)KDOF;

    out[0] = 0.5f * __logf(two_k / var)
           + (var + dm * dm) / (2.0f * two_k)
           - 0.5f;

    // Reset scratch for next graph replay.
    g_m.s1 = 0.0f;
    g_m.s2 = 0.0f;
    g_count = 0;
}

extern "C" void kernel_launch(void* const* d_in, const int* in_sizes, int n_in,
                              void* d_out, int out_size)
{
    const float* y   = (const float*)d_in[0];
    const float* mu  = (const float*)d_in[1];
    const float* sd  = (const float*)d_in[2];
    const int*   idx = (const int*)d_in[3];
    float* out = (float*)d_out;

    fused_chi2_kl_kernel<<<NUM_SAMPLES, 128>>>(y, mu, sd, idx, out);
}

// round 11
// speedup vs baseline: 1.0323x; 1.0323x over previous
#include <cuda_runtime.h>
#include <math.h>

// Inputs (metadata order): y[16M] f32, mu[16M] f32, std[16M] f32, idx[200*100] i32
// Output: 1 x f32 (KL scalar)
//
// FINAL converged kernel (re-submission of the session-best measured variant).
// Rationale from 10 rounds of measurement:
//   - Wall time is pinned at the harness graph-replay floor (~8.7 us +- 0.3);
//     kernel-side deltas of ~1 us are invisible. Only pessimizations (fp64
//     tail, single-warp gather) reproducibly cost time.
//   - Best measured configuration: 200 blocks x 128 threads, threads 0..99
//     gather one (y,mu,sd) triple (coalesced idx row read, MLP=3), in-block
//     shfl+smem reduce, fp32 shifted-moment global atomics (q-K kills the
//     variance cancellation so fp32 suffices), last-block ticket computes
//     the KL scalar with fp32 MUFU math.

#define NUM_SAMPLES 200
#define KDOF 100

// Scratch (no device allocation allowed). Winner resets for next graph replay.
__device__ float        g_s1 = 0.0f;   // sum of (q - K)
__device__ float        g_s2 = 0.0f;   // sum of (q - K)^2
__device__ unsigned int g_count = 0;

__global__ void __launch_bounds__(128) fused_chi2_kl_kernel(
    const float* __restrict__ y,
    const float* __restrict__ mu,
    const float* __restrict__ sd,
    const int*   __restrict__ idx,
    float*       __restrict__ out)
{
    const int s = blockIdx.x;
    const int t = threadIdx.x;

    // ---- Phase 1: per-sample chi-square statistic ----
    float v = 0.0f;
    if (t < KDOF) {
        const int i = idx[s * KDOF + t];   // coalesced 400B row, chain head
        // three independent gathers -> MLP=3 per thread
        const float d = __fdividef(y[i] - mu[i], sd[i]);
        v = d * d;
    }

    #pragma unroll
    for (int o = 16; o > 0; o >>= 1)
        v += __shfl_down_sync(0xFFFFFFFFu, v, o);

    __shared__ float sm[4];
    if ((t & 31) == 0) sm[t >> 5] = v;
    __syncthreads();

    if (t != 0) return;

    // Shifted statistic: p = q - K (kills cancellation in the var formula)
    const float p = (sm[0] + sm[1] + sm[2] + sm[3]) - (float)KDOF;

    atomicAdd(&g_s1, p);
    atomicAdd(&g_s2, p * p);
    __threadfence();                            // publish sums before ticket

    if (atomicAdd(&g_count, 1u) != NUM_SAMPLES - 1u) return;

    // ---- Phase 2 (single thread, last block): KL from shifted moments ----
    __threadfence();                            // acquire: see all atomic sums

    const float s1 = g_s1;
    const float s2 = g_s2;

    const float inv_n  = 1.0f / (float)NUM_SAMPLES;
    const float dm     = s1 * inv_n;                          // emp_mu - K
    const float var    = (s2 - s1 * s1 * inv_n)
                         * (1.0f / (float)(NUM_SAMPLES - 1)); // unbiased var
    const float two_k  = 2.0f * (float)KDOF;

    out[0] = 0.5f * __logf(two_k / var)
           + (var + dm * dm) / (2.0f * two_k)
           - 0.5f;

    // Reset scratch for next replay.
    g_s1 = 0.0f;
    g_s2 = 0.0f;
    g_count = 0;
}

extern "C" void kernel_launch(void* const* d_in, const int* in_sizes, int n_in,
                              void* d_out, int out_size)
{
    const float* y   = (const float*)d_in[0];
    const float* mu  = (const float*)d_in[1];
    const float* sd  = (const float*)d_in[2];
    const int*   idx = (const int*)d_in[3];
    float* out = (float*)d_out;

    fused_chi2_kl_kernel<<<NUM_SAMPLES, 128>>>(y, mu, sd, idx, out);
}

// round 12
// speedup vs baseline: 1.0588x; 1.0257x over previous
#include <cuda_runtime.h>
#include <math.h>

// Inputs (metadata order): y[16M] f32, mu[16M] f32, std[16M] f32, idx[200*100] i32
// Output: 1 x f32 (KL scalar)
//
// CONVERGED FINAL KERNEL — 11 rounds of evidence:
//   - Wall is pinned at the harness graph-replay floor (~8.7 us +- 0.3 jitter);
//     identical sources measured 8.672 and 8.928 on different runs.
//   - No hardware pipe exceeds ~13% in any profile; the kernel's real
//     execution is a ~1-2 us gather-latency chain hidden under the floor.
//   - Reproducible pessimizations (avoided): fp64 single-thread tail (+2.3us),
//     single-warp-per-sample gather (+2.3us, load-queue serialization).
//   - Chain-minimal design: 200 blocks x 128 threads; threads 0..99 gather one
//     (y,mu,sd) triple (coalesced idx row, MLP=3), shfl+smem block reduce,
//     fp32 shifted-moment global atomics (q-K removes variance cancellation),
//     ticketed last block computes KL with fp32 MUFU math.

#define NUM_SAMPLES 200
#define KDOF 100

// Scratch (no device allocation allowed). Winner resets for next graph replay.
__device__ float        g_s1 = 0.0f;   // sum of (q - K)
__device__ float        g_s2 = 0.0f;   // sum of (q - K)^2
__device__ unsigned int g_count = 0;

__global__ void __launch_bounds__(128) fused_chi2_kl_kernel(
    const float* __restrict__ y,
    const float* __restrict__ mu,
    const float* __restrict__ sd,
    const int*   __restrict__ idx,
    float*       __restrict__ out)
{
    const int s = blockIdx.x;
    const int t = threadIdx.x;

    // ---- Phase 1: per-sample chi-square statistic ----
    float v = 0.0f;
    if (t < KDOF) {
        const int i = idx[s * KDOF + t];   // coalesced 400B row, chain head
        // three independent gathers -> MLP=3 per thread
        const float d = __fdividef(y[i] - mu[i], sd[i]);
        v = d * d;
    }

    #pragma unroll
    for (int o = 16; o > 0; o >>= 1)
        v += __shfl_down_sync(0xFFFFFFFFu, v, o);

    __shared__ float sm[4];
    if ((t & 31) == 0) sm[t >> 5] = v;
    __syncthreads();

    if (t != 0) return;

    // Shifted statistic: p = q - K (kills cancellation in the var formula)
    const float p = (sm[0] + sm[1] + sm[2] + sm[3]) - (float)KDOF;

    atomicAdd(&g_s1, p);
    atomicAdd(&g_s2, p * p);
    __threadfence();                            // publish sums before ticket

    if (atomicAdd(&g_count, 1u) != NUM_SAMPLES - 1u) return;

    // ---- Phase 2 (single thread, last block): KL from shifted moments ----
    __threadfence();                            // acquire: see all atomic sums

    const float s1 = g_s1;
    const float s2 = g_s2;

    const float inv_n  = 1.0f / (float)NUM_SAMPLES;
    const float dm     = s1 * inv_n;                          // emp_mu - K
    const float var    = (s2 - s1 * s1 * inv_n)
                         * (1.0f / (float)(NUM_SAMPLES - 1)); // unbiased var
    const float two_k  = 2.0f * (float)KDOF;

    out[0] = 0.5f * __logf(two_k / var)
           + (var + dm * dm) / (2.0f * two_k)
           - 0.5f;

    // Reset scratch for next replay.
    g_s1 = 0.0f;
    g_s2 = 0.0f;
    g_count = 0;
}

extern "C" void kernel_launch(void* const* d_in, const int* in_sizes, int n_in,
                              void* d_out, int out_size)
{
    const float* y   = (const float*)d_in[0];
    const float* mu  = (const float*)d_in[1];
    const float* sd  = (const float*)d_in[2];
    const int*   idx = (const int*)d_in[3];
    float* out = (float*)d_out;

    fused_chi2_kl_kernel<<<NUM_SAMPLES, 128>>>(y, mu, sd, idx, out);
}